// round 14
// baseline (speedup 1.0000x reference)
#include <cuda_runtime.h>

// 7-level db4 DWT -> soft threshold -> IDWT, fully fused in SMEM.
// R14 = R13 (160 threads, 10 barrier slots) + __launch_bounds__(160, 10)
// pinning the ptxas register budget to 40 (R4's natural allocation).

#define NTHREADS 160
#define NROWS    32768
#define N0       1116

static __constant__ float DLO[8] = {
    -0.010597401784997278f,  0.032883011666982945f,  0.030841381835986965f,
    -0.18703481171888114f,  -0.02798376941698385f,   0.6308807679295904f,
     0.7148465705525415f,    0.23037781330885523f
};
static __constant__ float DHI[8] = {
    -0.23037781330885523f,   0.7148465705525415f,   -0.6308807679295904f,
    -0.02798376941698385f,   0.18703481171888114f,   0.030841381835986965f,
    -0.032883011666982945f, -0.010597401784997278f
};

__device__ __forceinline__ float softf(float c, float t) {
    return copysignf(fmaxf(fabsf(c) - t, 0.0f), c);
}

// ---- forward level 1: read row directly from gmem (zero-extended).
template<int NTH>
__device__ __forceinline__ void fwd_gmem(const float* __restrict__ x,
                                         float* __restrict__ an,
                                         float* __restrict__ dph,
                                         float thr, int tid)
{
    constexpr int M   = 561;
    constexpr int PAD = (M + 1) / 2 + 8;   // 289
    for (int t = tid; t < PAD; t += NTH) {
        float r[16];
        const int b0 = 4 * t - 8;
        if (t >= 2 && t < 278) {
            #pragma unroll
            for (int bi = 0; bi < 4; bi++)
                *(float4*)(r + 4 * bi) = *(const float4*)(x + b0 + 4 * bi);
        } else {
            #pragma unroll
            for (int bi = 0; bi < 4; bi++) {
                const int idx = b0 + 4 * bi;
                float4 v = make_float4(0.f, 0.f, 0.f, 0.f);
                if (idx >= 0 && idx + 4 <= N0) v = *(const float4*)(x + idx);
                *(float4*)(r + 4 * bi) = v;
            }
        }
        float ca0 = 0.f, cd0 = 0.f, ca1 = 0.f, cd1 = 0.f;
        #pragma unroll
        for (int k = 0; k < 8; k++) {
            ca0 = fmaf(r[2 + k], DLO[7 - k], ca0);
            cd0 = fmaf(r[2 + k], DHI[7 - k], cd0);
            ca1 = fmaf(r[4 + k], DLO[7 - k], ca1);
            cd1 = fmaf(r[4 + k], DHI[7 - k], cd1);
        }
        cd0 = softf(cd0, thr); cd1 = softf(cd1, thr);
        const int j0 = 2 * t;
        *(float2*)(an + 6 + j0) = make_float2(j0 < M ? ca0 : 0.f,
                                              (j0 + 1) < M ? ca1 : 0.f);
        if (j0 < M)
            *(float2*)(dph + j0) = make_float2(cd0, (j0 + 1) < M ? cd1 : 0.f);
    }
}

// ---- forward SMEM level, 2 outputs/unit, dense 16B-stride LDS.128.
template<int M, bool LAST, int NTH>
__device__ __forceinline__ void fwd_level(const float* __restrict__ a,
                                          float* __restrict__ an,
                                          float* __restrict__ dph,
                                          float thr, int tid)
{
    constexpr int PAD = (M + 1) / 2 + 8;
    for (int t = tid; t < PAD; t += NTH) {
        float r[12];
        *(float4*)(r)     = *(const float4*)(a + 4 * t);
        *(float4*)(r + 4) = *(const float4*)(a + 4 * t + 4);
        *(float4*)(r + 8) = *(const float4*)(a + 4 * t + 8);
        float ca0 = 0.f, cd0 = 0.f, ca1 = 0.f, cd1 = 0.f;
        #pragma unroll
        for (int k = 0; k < 8; k++) {
            ca0 = fmaf(r[k],     DLO[7 - k], ca0);
            cd0 = fmaf(r[k],     DHI[7 - k], cd0);
            ca1 = fmaf(r[k + 2], DLO[7 - k], ca1);
            cd1 = fmaf(r[k + 2], DHI[7 - k], cd1);
        }
        cd0 = softf(cd0, thr); cd1 = softf(cd1, thr);
        if (LAST) { ca0 = softf(ca0, thr); ca1 = softf(ca1, thr); }
        const int j0 = 2 * t;
        *(float2*)(an + 6 + j0) = make_float2(j0 < M ? ca0 : 0.f,
                                              (j0 + 1) < M ? ca1 : 0.f);
        if (j0 < M)
            *(float2*)(dph + j0) = make_float2(cd0, (j0 + 1) < M ? cd1 : 0.f);
    }
}

// ---- inverse level, 4 outputs/unit, dense 8B-stride loads, 16B stores.
template<int MD, int NTH>
__device__ __forceinline__ void inv_level(const float* __restrict__ a,
                                          const float* __restrict__ d,
                                          float* __restrict__ o, int tid)
{
    constexpr int OLEN  = 2 * MD - 6;
    constexpr int QUADS = (OLEN + 3) / 4;
    for (int u = tid; u < QUADS; u += NTH) {
        const int s = 2 * u;
        const float2 a01 = *(const float2*)(a + s);
        const float2 a23 = *(const float2*)(a + s + 2);
        const float  a4  = a[s + 4];
        const float2 d01 = *(const float2*)(d + s);
        const float2 d23 = *(const float2*)(d + s + 2);
        const float  d4  = d[s + 4];
        float o0 = a01.x * DLO[1];  o0 = fmaf(a01.y, DLO[3], o0);
        o0 = fmaf(a23.x, DLO[5], o0); o0 = fmaf(a23.y, DLO[7], o0);
        o0 = fmaf(d01.x, DHI[1], o0); o0 = fmaf(d01.y, DHI[3], o0);
        o0 = fmaf(d23.x, DHI[5], o0); o0 = fmaf(d23.y, DHI[7], o0);
        float o1 = a01.x * DLO[0];  o1 = fmaf(a01.y, DLO[2], o1);
        o1 = fmaf(a23.x, DLO[4], o1); o1 = fmaf(a23.y, DLO[6], o1);
        o1 = fmaf(d01.x, DHI[0], o1); o1 = fmaf(d01.y, DHI[2], o1);
        o1 = fmaf(d23.x, DHI[4], o1); o1 = fmaf(d23.y, DHI[6], o1);
        float o2 = a01.y * DLO[1];  o2 = fmaf(a23.x, DLO[3], o2);
        o2 = fmaf(a23.y, DLO[5], o2); o2 = fmaf(a4,   DLO[7], o2);
        o2 = fmaf(d01.y, DHI[1], o2); o2 = fmaf(d23.x, DHI[3], o2);
        o2 = fmaf(d23.y, DHI[5], o2); o2 = fmaf(d4,   DHI[7], o2);
        float o3 = a01.y * DLO[0];  o3 = fmaf(a23.x, DLO[2], o3);
        o3 = fmaf(a23.y, DLO[4], o3); o3 = fmaf(a4,   DLO[6], o3);
        o3 = fmaf(d01.y, DHI[0], o3); o3 = fmaf(d23.x, DHI[2], o3);
        o3 = fmaf(d23.y, DHI[4], o3); o3 = fmaf(d4,   DHI[6], o3);
        if (4 * u + 3 < OLEN) *(float4*)(o + 4 * u) = make_float4(o0, o1, o2, o3);
        else                  *(float2*)(o + 4 * u) = make_float2(o0, o1);
    }
}

__global__ __launch_bounds__(NTHREADS, 10)
void wavelet_fused_kernel(const float* __restrict__ x,
                          const float* __restrict__ rawthr,
                          float* __restrict__ out)
{
    // Level lengths: {1116, 561, 284, 145, 76, 41, 24, 15}
    __shared__ __align__(16) float sA[1168];
    __shared__ __align__(16) float sB[640];
    __shared__ __align__(16) float sD[1152];  // doff: 0,562,846,992,1068,1110,1134

    const int row = blockIdx.x;
    const int tid = threadIdx.x;
    const float thr = fmaxf(__ldg(rawthr), 0.01f);
    const float* __restrict__ xr = x + (size_t)row * N0;

    // residual zero-fill (regions never overwritten before their reads)
    if (tid < 6)       { sA[tid] = 0.f; sB[tid] = 0.f; }
    if (tid >= 64 && tid < 64 + 56) sB[520 + tid] = 0.f;   // sB[584..640)
    __syncthreads();

    // ---- forward DWT (level 1 straight from gmem)
    fwd_gmem<NTHREADS>(xr, sB, sD + 0, thr, tid);                 __syncthreads();
    fwd_level<284, false, NTHREADS>(sB, sA, sD + 562, thr, tid);  __syncthreads();
    fwd_level<145, false, NTHREADS>(sA, sB, sD + 846, thr, tid);  __syncthreads();
    fwd_level<76,  false, NTHREADS>(sB, sA, sD + 992, thr, tid);  __syncthreads();

    // ---- tiny levels: single warp, __syncwarp only
    if (tid < 32) {
        fwd_level<41, false, 32>(sA, sB, sD + 1068, thr, tid); __syncwarp();
        fwd_level<24, false, 32>(sB, sA, sD + 1110, thr, tid); __syncwarp();
        fwd_level<15, true,  32>(sA, sB, sD + 1134, thr, tid); __syncwarp();
        inv_level<15, 32>(sB + 6, sD + 1134, sA + 8, tid);     __syncwarp();
        inv_level<24, 32>(sA + 8, sD + 1110, sB + 8, tid);     __syncwarp();
        inv_level<41, 32>(sB + 8, sD + 1068, sA + 8, tid);
    }
    __syncthreads();

    // ---- inverse DWT, big levels; final level streams to gmem (1116 % 4 == 0)
    inv_level<76,  NTHREADS>(sA + 8, sD + 992, sB + 8, tid); __syncthreads();
    inv_level<145, NTHREADS>(sB + 8, sD + 846, sA + 8, tid); __syncthreads();
    inv_level<284, NTHREADS>(sA + 8, sD + 562, sB + 8, tid); __syncthreads();
    inv_level<561, NTHREADS>(sB + 8, sD + 0, out + (size_t)row * N0, tid);
}

extern "C" void kernel_launch(void* const* d_in, const int* in_sizes, int n_in,
                              void* d_out, int out_size)
{
    const float* x    = (const float*)d_in[0];
    const float* rthr = (const float*)d_in[1];
    float* out        = (float*)d_out;
    wavelet_fused_kernel<<<NROWS, NTHREADS>>>(x, rthr, out);
}

// round 15
// speedup vs baseline: 1.3091x; 1.3091x over previous
#include <cuda_runtime.h>

// 7-level db4 DWT -> soft threshold -> IDWT, fully fused in SMEM.
// R15 = R4 + __launch_bounds__(128,14) (36-reg budget -> 14 CTAs/SM, 56 warps)
//     + initial zero-fill barrier merged away (write-disjoint with fwd_gmem).

#define NTHREADS 128
#define NROWS    32768
#define N0       1116

static __constant__ float DLO[8] = {
    -0.010597401784997278f,  0.032883011666982945f,  0.030841381835986965f,
    -0.18703481171888114f,  -0.02798376941698385f,   0.6308807679295904f,
     0.7148465705525415f,    0.23037781330885523f
};
static __constant__ float DHI[8] = {
    -0.23037781330885523f,   0.7148465705525415f,   -0.6308807679295904f,
    -0.02798376941698385f,   0.18703481171888114f,   0.030841381835986965f,
    -0.032883011666982945f, -0.010597401784997278f
};

__device__ __forceinline__ float softf(float c, float t) {
    return copysignf(fmaxf(fabsf(c) - t, 0.0f), c);
}

// ---- forward level 1: read row directly from gmem (zero-extended).
template<int NTH>
__device__ __forceinline__ void fwd_gmem(const float* __restrict__ x,
                                         float* __restrict__ an,
                                         float* __restrict__ dph,
                                         float thr, int tid)
{
    constexpr int M   = 561;
    constexpr int PAD = (M + 1) / 2 + 8;   // 289
    for (int t = tid; t < PAD; t += NTH) {
        float r[16];
        const int b0 = 4 * t - 8;
        if (t >= 2 && t < 278) {
            #pragma unroll
            for (int bi = 0; bi < 4; bi++)
                *(float4*)(r + 4 * bi) = *(const float4*)(x + b0 + 4 * bi);
        } else {
            #pragma unroll
            for (int bi = 0; bi < 4; bi++) {
                const int idx = b0 + 4 * bi;
                float4 v = make_float4(0.f, 0.f, 0.f, 0.f);
                if (idx >= 0 && idx + 4 <= N0) v = *(const float4*)(x + idx);
                *(float4*)(r + 4 * bi) = v;
            }
        }
        float ca0 = 0.f, cd0 = 0.f, ca1 = 0.f, cd1 = 0.f;
        #pragma unroll
        for (int k = 0; k < 8; k++) {
            ca0 = fmaf(r[2 + k], DLO[7 - k], ca0);
            cd0 = fmaf(r[2 + k], DHI[7 - k], cd0);
            ca1 = fmaf(r[4 + k], DLO[7 - k], ca1);
            cd1 = fmaf(r[4 + k], DHI[7 - k], cd1);
        }
        cd0 = softf(cd0, thr); cd1 = softf(cd1, thr);
        const int j0 = 2 * t;
        *(float2*)(an + 6 + j0) = make_float2(j0 < M ? ca0 : 0.f,
                                              (j0 + 1) < M ? ca1 : 0.f);
        if (j0 < M)
            *(float2*)(dph + j0) = make_float2(cd0, (j0 + 1) < M ? cd1 : 0.f);
    }
}

// ---- forward SMEM level, 2 outputs/unit, dense 16B-stride LDS.128.
template<int M, bool LAST, int NTH>
__device__ __forceinline__ void fwd_level(const float* __restrict__ a,
                                          float* __restrict__ an,
                                          float* __restrict__ dph,
                                          float thr, int tid)
{
    constexpr int PAD = (M + 1) / 2 + 8;
    for (int t = tid; t < PAD; t += NTH) {
        float r[12];
        *(float4*)(r)     = *(const float4*)(a + 4 * t);
        *(float4*)(r + 4) = *(const float4*)(a + 4 * t + 4);
        *(float4*)(r + 8) = *(const float4*)(a + 4 * t + 8);
        float ca0 = 0.f, cd0 = 0.f, ca1 = 0.f, cd1 = 0.f;
        #pragma unroll
        for (int k = 0; k < 8; k++) {
            ca0 = fmaf(r[k],     DLO[7 - k], ca0);
            cd0 = fmaf(r[k],     DHI[7 - k], cd0);
            ca1 = fmaf(r[k + 2], DLO[7 - k], ca1);
            cd1 = fmaf(r[k + 2], DHI[7 - k], cd1);
        }
        cd0 = softf(cd0, thr); cd1 = softf(cd1, thr);
        if (LAST) { ca0 = softf(ca0, thr); ca1 = softf(ca1, thr); }
        const int j0 = 2 * t;
        *(float2*)(an + 6 + j0) = make_float2(j0 < M ? ca0 : 0.f,
                                              (j0 + 1) < M ? ca1 : 0.f);
        if (j0 < M)
            *(float2*)(dph + j0) = make_float2(cd0, (j0 + 1) < M ? cd1 : 0.f);
    }
}

// ---- inverse level, 4 outputs/unit, dense 8B-stride loads, 16B stores.
template<int MD, int NTH>
__device__ __forceinline__ void inv_level(const float* __restrict__ a,
                                          const float* __restrict__ d,
                                          float* __restrict__ o, int tid)
{
    constexpr int OLEN  = 2 * MD - 6;
    constexpr int QUADS = (OLEN + 3) / 4;
    for (int u = tid; u < QUADS; u += NTH) {
        const int s = 2 * u;
        const float2 a01 = *(const float2*)(a + s);
        const float2 a23 = *(const float2*)(a + s + 2);
        const float  a4  = a[s + 4];
        const float2 d01 = *(const float2*)(d + s);
        const float2 d23 = *(const float2*)(d + s + 2);
        const float  d4  = d[s + 4];
        float o0 = a01.x * DLO[1];  o0 = fmaf(a01.y, DLO[3], o0);
        o0 = fmaf(a23.x, DLO[5], o0); o0 = fmaf(a23.y, DLO[7], o0);
        o0 = fmaf(d01.x, DHI[1], o0); o0 = fmaf(d01.y, DHI[3], o0);
        o0 = fmaf(d23.x, DHI[5], o0); o0 = fmaf(d23.y, DHI[7], o0);
        float o1 = a01.x * DLO[0];  o1 = fmaf(a01.y, DLO[2], o1);
        o1 = fmaf(a23.x, DLO[4], o1); o1 = fmaf(a23.y, DLO[6], o1);
        o1 = fmaf(d01.x, DHI[0], o1); o1 = fmaf(d01.y, DHI[2], o1);
        o1 = fmaf(d23.x, DHI[4], o1); o1 = fmaf(d23.y, DHI[6], o1);
        float o2 = a01.y * DLO[1];  o2 = fmaf(a23.x, DLO[3], o2);
        o2 = fmaf(a23.y, DLO[5], o2); o2 = fmaf(a4,   DLO[7], o2);
        o2 = fmaf(d01.y, DHI[1], o2); o2 = fmaf(d23.x, DHI[3], o2);
        o2 = fmaf(d23.y, DHI[5], o2); o2 = fmaf(d4,   DHI[7], o2);
        float o3 = a01.y * DLO[0];  o3 = fmaf(a23.x, DLO[2], o3);
        o3 = fmaf(a23.y, DLO[4], o3); o3 = fmaf(a4,   DLO[6], o3);
        o3 = fmaf(d01.y, DHI[0], o3); o3 = fmaf(d23.x, DHI[2], o3);
        o3 = fmaf(d23.y, DHI[4], o3); o3 = fmaf(d4,   DHI[6], o3);
        if (4 * u + 3 < OLEN) *(float4*)(o + 4 * u) = make_float4(o0, o1, o2, o3);
        else                  *(float2*)(o + 4 * u) = make_float2(o0, o1);
    }
}

__global__ __launch_bounds__(NTHREADS, 14)
void wavelet_fused_kernel(const float* __restrict__ x,
                          const float* __restrict__ rawthr,
                          float* __restrict__ out)
{
    // Level lengths: {1116, 561, 284, 145, 76, 41, 24, 15}
    __shared__ __align__(16) float sA[1168];
    __shared__ __align__(16) float sB[640];
    __shared__ __align__(16) float sD[1152];  // doff: 0,562,846,992,1068,1110,1134

    const int row = blockIdx.x;
    const int tid = threadIdx.x;
    const float thr = fmaxf(__ldg(rawthr), 0.01f);
    const float* __restrict__ xr = x + (size_t)row * N0;

    // residual zero-fill: disjoint from fwd_gmem's write range [6,584) of sB,
    // so NO barrier needed before fwd_gmem — the barrier after it orders these
    // zeros for all later readers (fwd<284>, fwd<145>, ...).
    if (tid < 6)       { sA[tid] = 0.f; sB[tid] = 0.f; }
    if (tid >= 64 && tid < 64 + 56) sB[520 + tid] = 0.f;   // sB[584..640)

    // ---- forward DWT (level 1 straight from gmem)
    fwd_gmem<NTHREADS>(xr, sB, sD + 0, thr, tid);                 __syncthreads();
    fwd_level<284, false, NTHREADS>(sB, sA, sD + 562, thr, tid);  __syncthreads();
    fwd_level<145, false, NTHREADS>(sA, sB, sD + 846, thr, tid);  __syncthreads();
    fwd_level<76,  false, NTHREADS>(sB, sA, sD + 992, thr, tid);  __syncthreads();

    // ---- tiny levels: single warp, __syncwarp only
    if (tid < 32) {
        fwd_level<41, false, 32>(sA, sB, sD + 1068, thr, tid); __syncwarp();
        fwd_level<24, false, 32>(sB, sA, sD + 1110, thr, tid); __syncwarp();
        fwd_level<15, true,  32>(sA, sB, sD + 1134, thr, tid); __syncwarp();
        inv_level<15, 32>(sB + 6, sD + 1134, sA + 8, tid);     __syncwarp();
        inv_level<24, 32>(sA + 8, sD + 1110, sB + 8, tid);     __syncwarp();
        inv_level<41, 32>(sB + 8, sD + 1068, sA + 8, tid);
    }
    __syncthreads();

    // ---- inverse DWT, big levels; final level streams to gmem (1116 % 4 == 0)
    inv_level<76,  NTHREADS>(sA + 8, sD + 992, sB + 8, tid); __syncthreads();
    inv_level<145, NTHREADS>(sB + 8, sD + 846, sA + 8, tid); __syncthreads();
    inv_level<284, NTHREADS>(sA + 8, sD + 562, sB + 8, tid); __syncthreads();
    inv_level<561, NTHREADS>(sB + 8, sD + 0, out + (size_t)row * N0, tid);
}

extern "C" void kernel_launch(void* const* d_in, const int* in_sizes, int n_in,
                              void* d_out, int out_size)
{
    const float* x    = (const float*)d_in[0];
    const float* rthr = (const float*)d_in[1];
    float* out        = (float*)d_out;
    wavelet_fused_kernel<<<NROWS, NTHREADS>>>(x, rthr, out);
}

// round 16
// speedup vs baseline: 1.3175x; 1.0064x over previous
#include <cuda_runtime.h>

// 7-level db4 DWT -> soft threshold -> IDWT, fully fused in SMEM.
// R16 = R15 (best, 105.2us) with __launch_bounds__(128,16): same 32-reg
// budget ptxas already chose, residency cap raised 14 -> 16 CTAs/SM.

#define NTHREADS 128
#define NROWS    32768
#define N0       1116

static __constant__ float DLO[8] = {
    -0.010597401784997278f,  0.032883011666982945f,  0.030841381835986965f,
    -0.18703481171888114f,  -0.02798376941698385f,   0.6308807679295904f,
     0.7148465705525415f,    0.23037781330885523f
};
static __constant__ float DHI[8] = {
    -0.23037781330885523f,   0.7148465705525415f,   -0.6308807679295904f,
    -0.02798376941698385f,   0.18703481171888114f,   0.030841381835986965f,
    -0.032883011666982945f, -0.010597401784997278f
};

__device__ __forceinline__ float softf(float c, float t) {
    return copysignf(fmaxf(fabsf(c) - t, 0.0f), c);
}

// ---- forward level 1: read row directly from gmem (zero-extended).
template<int NTH>
__device__ __forceinline__ void fwd_gmem(const float* __restrict__ x,
                                         float* __restrict__ an,
                                         float* __restrict__ dph,
                                         float thr, int tid)
{
    constexpr int M   = 561;
    constexpr int PAD = (M + 1) / 2 + 8;   // 289
    for (int t = tid; t < PAD; t += NTH) {
        float r[16];
        const int b0 = 4 * t - 8;
        if (t >= 2 && t < 278) {
            #pragma unroll
            for (int bi = 0; bi < 4; bi++)
                *(float4*)(r + 4 * bi) = *(const float4*)(x + b0 + 4 * bi);
        } else {
            #pragma unroll
            for (int bi = 0; bi < 4; bi++) {
                const int idx = b0 + 4 * bi;
                float4 v = make_float4(0.f, 0.f, 0.f, 0.f);
                if (idx >= 0 && idx + 4 <= N0) v = *(const float4*)(x + idx);
                *(float4*)(r + 4 * bi) = v;
            }
        }
        float ca0 = 0.f, cd0 = 0.f, ca1 = 0.f, cd1 = 0.f;
        #pragma unroll
        for (int k = 0; k < 8; k++) {
            ca0 = fmaf(r[2 + k], DLO[7 - k], ca0);
            cd0 = fmaf(r[2 + k], DHI[7 - k], cd0);
            ca1 = fmaf(r[4 + k], DLO[7 - k], ca1);
            cd1 = fmaf(r[4 + k], DHI[7 - k], cd1);
        }
        cd0 = softf(cd0, thr); cd1 = softf(cd1, thr);
        const int j0 = 2 * t;
        *(float2*)(an + 6 + j0) = make_float2(j0 < M ? ca0 : 0.f,
                                              (j0 + 1) < M ? ca1 : 0.f);
        if (j0 < M)
            *(float2*)(dph + j0) = make_float2(cd0, (j0 + 1) < M ? cd1 : 0.f);
    }
}

// ---- forward SMEM level, 2 outputs/unit, dense 16B-stride LDS.128.
template<int M, bool LAST, int NTH>
__device__ __forceinline__ void fwd_level(const float* __restrict__ a,
                                          float* __restrict__ an,
                                          float* __restrict__ dph,
                                          float thr, int tid)
{
    constexpr int PAD = (M + 1) / 2 + 8;
    for (int t = tid; t < PAD; t += NTH) {
        float r[12];
        *(float4*)(r)     = *(const float4*)(a + 4 * t);
        *(float4*)(r + 4) = *(const float4*)(a + 4 * t + 4);
        *(float4*)(r + 8) = *(const float4*)(a + 4 * t + 8);
        float ca0 = 0.f, cd0 = 0.f, ca1 = 0.f, cd1 = 0.f;
        #pragma unroll
        for (int k = 0; k < 8; k++) {
            ca0 = fmaf(r[k],     DLO[7 - k], ca0);
            cd0 = fmaf(r[k],     DHI[7 - k], cd0);
            ca1 = fmaf(r[k + 2], DLO[7 - k], ca1);
            cd1 = fmaf(r[k + 2], DHI[7 - k], cd1);
        }
        cd0 = softf(cd0, thr); cd1 = softf(cd1, thr);
        if (LAST) { ca0 = softf(ca0, thr); ca1 = softf(ca1, thr); }
        const int j0 = 2 * t;
        *(float2*)(an + 6 + j0) = make_float2(j0 < M ? ca0 : 0.f,
                                              (j0 + 1) < M ? ca1 : 0.f);
        if (j0 < M)
            *(float2*)(dph + j0) = make_float2(cd0, (j0 + 1) < M ? cd1 : 0.f);
    }
}

// ---- inverse level, 4 outputs/unit, dense 8B-stride loads, 16B stores.
template<int MD, int NTH>
__device__ __forceinline__ void inv_level(const float* __restrict__ a,
                                          const float* __restrict__ d,
                                          float* __restrict__ o, int tid)
{
    constexpr int OLEN  = 2 * MD - 6;
    constexpr int QUADS = (OLEN + 3) / 4;
    for (int u = tid; u < QUADS; u += NTH) {
        const int s = 2 * u;
        const float2 a01 = *(const float2*)(a + s);
        const float2 a23 = *(const float2*)(a + s + 2);
        const float  a4  = a[s + 4];
        const float2 d01 = *(const float2*)(d + s);
        const float2 d23 = *(const float2*)(d + s + 2);
        const float  d4  = d[s + 4];
        float o0 = a01.x * DLO[1];  o0 = fmaf(a01.y, DLO[3], o0);
        o0 = fmaf(a23.x, DLO[5], o0); o0 = fmaf(a23.y, DLO[7], o0);
        o0 = fmaf(d01.x, DHI[1], o0); o0 = fmaf(d01.y, DHI[3], o0);
        o0 = fmaf(d23.x, DHI[5], o0); o0 = fmaf(d23.y, DHI[7], o0);
        float o1 = a01.x * DLO[0];  o1 = fmaf(a01.y, DLO[2], o1);
        o1 = fmaf(a23.x, DLO[4], o1); o1 = fmaf(a23.y, DLO[6], o1);
        o1 = fmaf(d01.x, DHI[0], o1); o1 = fmaf(d01.y, DHI[2], o1);
        o1 = fmaf(d23.x, DHI[4], o1); o1 = fmaf(d23.y, DHI[6], o1);
        float o2 = a01.y * DLO[1];  o2 = fmaf(a23.x, DLO[3], o2);
        o2 = fmaf(a23.y, DLO[5], o2); o2 = fmaf(a4,   DLO[7], o2);
        o2 = fmaf(d01.y, DHI[1], o2); o2 = fmaf(d23.x, DHI[3], o2);
        o2 = fmaf(d23.y, DHI[5], o2); o2 = fmaf(d4,   DHI[7], o2);
        float o3 = a01.y * DLO[0];  o3 = fmaf(a23.x, DLO[2], o3);
        o3 = fmaf(a23.y, DLO[4], o3); o3 = fmaf(a4,   DLO[6], o3);
        o3 = fmaf(d01.y, DHI[0], o3); o3 = fmaf(d23.x, DHI[2], o3);
        o3 = fmaf(d23.y, DHI[4], o3); o3 = fmaf(d4,   DHI[6], o3);
        if (4 * u + 3 < OLEN) *(float4*)(o + 4 * u) = make_float4(o0, o1, o2, o3);
        else                  *(float2*)(o + 4 * u) = make_float2(o0, o1);
    }
}

__global__ __launch_bounds__(NTHREADS, 16)
void wavelet_fused_kernel(const float* __restrict__ x,
                          const float* __restrict__ rawthr,
                          float* __restrict__ out)
{
    // Level lengths: {1116, 561, 284, 145, 76, 41, 24, 15}
    __shared__ __align__(16) float sA[1168];
    __shared__ __align__(16) float sB[640];
    __shared__ __align__(16) float sD[1152];  // doff: 0,562,846,992,1068,1110,1134

    const int row = blockIdx.x;
    const int tid = threadIdx.x;
    const float thr = fmaxf(__ldg(rawthr), 0.01f);
    const float* __restrict__ xr = x + (size_t)row * N0;

    // residual zero-fill: disjoint from fwd_gmem's write range [6,584) of sB,
    // so no barrier needed before fwd_gmem — the barrier after it orders these
    // zeros for all later readers.
    if (tid < 6)       { sA[tid] = 0.f; sB[tid] = 0.f; }
    if (tid >= 64 && tid < 64 + 56) sB[520 + tid] = 0.f;   // sB[584..640)

    // ---- forward DWT (level 1 straight from gmem)
    fwd_gmem<NTHREADS>(xr, sB, sD + 0, thr, tid);                 __syncthreads();
    fwd_level<284, false, NTHREADS>(sB, sA, sD + 562, thr, tid);  __syncthreads();
    fwd_level<145, false, NTHREADS>(sA, sB, sD + 846, thr, tid);  __syncthreads();
    fwd_level<76,  false, NTHREADS>(sB, sA, sD + 992, thr, tid);  __syncthreads();

    // ---- tiny levels: single warp, __syncwarp only
    if (tid < 32) {
        fwd_level<41, false, 32>(sA, sB, sD + 1068, thr, tid); __syncwarp();
        fwd_level<24, false, 32>(sB, sA, sD + 1110, thr, tid); __syncwarp();
        fwd_level<15, true,  32>(sA, sB, sD + 1134, thr, tid); __syncwarp();
        inv_level<15, 32>(sB + 6, sD + 1134, sA + 8, tid);     __syncwarp();
        inv_level<24, 32>(sA + 8, sD + 1110, sB + 8, tid);     __syncwarp();
        inv_level<41, 32>(sB + 8, sD + 1068, sA + 8, tid);
    }
    __syncthreads();

    // ---- inverse DWT, big levels; final level streams to gmem (1116 % 4 == 0)
    inv_level<76,  NTHREADS>(sA + 8, sD + 992, sB + 8, tid); __syncthreads();
    inv_level<145, NTHREADS>(sB + 8, sD + 846, sA + 8, tid); __syncthreads();
    inv_level<284, NTHREADS>(sA + 8, sD + 562, sB + 8, tid); __syncthreads();
    inv_level<561, NTHREADS>(sB + 8, sD + 0, out + (size_t)row * N0, tid);
}

extern "C" void kernel_launch(void* const* d_in, const int* in_sizes, int n_in,
                              void* d_out, int out_size)
{
    const float* x    = (const float*)d_in[0];
    const float* rthr = (const float*)d_in[1];
    float* out        = (float*)d_out;
    wavelet_fused_kernel<<<NROWS, NTHREADS>>>(x, rthr, out);
}